// round 9
// baseline (speedup 1.0000x reference)
#include <cuda_runtime.h>
#include <cuda_bf16.h>
#include <cstdint>
#include <cstddef>

// Problem constants
#define BATCH 4
#define NSEQ 2048
#define DIM 512
#define NHEAD 8
#define DHEAD 128
#define INNER 1024
#define MROWS (BATCH*NSEQ)  // 8192

#define WIN 16
#define TN 64
#define SMAX_S 6.0f          // fixed quant range for smoothed activations

// ---------------- scratch (allocation-free rule) ----------------
// int8 two-limb packed operands in mma fragment order.
// A atom = 16x32 s8 = 512B (lane*16: [a0,a1,a2,a3] 4B each).
// B atom = 8x32  s8 = 256B (lane*8:  [b0,b1]).
__device__ __align__(16) float   g_y[MROWS * INNER];
__device__ __align__(16) uint8_t g_x0[MROWS * DIM];
__device__ __align__(16) uint8_t g_x1[MROWS * DIM];
__device__ __align__(16) uint8_t g_s0[MROWS * INNER];
__device__ __align__(16) uint8_t g_s1[MROWS * INNER];
__device__ __align__(16) uint8_t g_w10[DIM * INNER];   // Wg^T limbs
__device__ __align__(16) uint8_t g_w11[DIM * INNER];
__device__ __align__(16) uint8_t g_w20[INNER * DIM];   // Wout^T limbs
__device__ __align__(16) uint8_t g_w21[INNER * DIM];
__device__ __align__(16) float g_sax[MROWS];   // step = rowmax/16256
__device__ __align__(16) float g_sb1[INNER];   // step per Wg col
__device__ __align__(16) float g_sb2[DIM];     // step per Wout col

// ---------------- helpers ----------------
typedef unsigned long long ull;
__device__ __forceinline__ ull pack_dup(float a) {
    ull r; asm("mov.b64 %0, {%1, %1};" : "=l"(r) : "f"(a)); return r;
}
__device__ __forceinline__ void ffma2(ull& d, ull a, ull b) {
    asm("fma.rn.f32x2 %0, %1, %2, %0;" : "+l"(d) : "l"(a), "l"(b));
}
__device__ __forceinline__ void unpack2(ull v, float& lo, float& hi) {
    asm("mov.b64 {%0, %1}, %2;" : "=f"(lo), "=f"(hi) : "l"(v));
}
__device__ __forceinline__ uint32_t smem_to_u32(const void* p) {
    uint32_t a;
    asm("{ .reg .u64 t; cvta.to.shared.u64 t, %1; cvt.u32.u64 %0, t; }" : "=r"(a) : "l"(p));
    return a;
}
__device__ __forceinline__ void cp16(uint32_t dst, const void* src) {
    asm volatile("cp.async.cg.shared.global [%0], [%1], 16;" :: "r"(dst), "l"(src) : "memory");
}
#define CP_COMMIT() asm volatile("cp.async.commit_group;" ::: "memory")
#define CP_WAIT1()  asm volatile("cp.async.wait_group 1;" ::: "memory")

__device__ __forceinline__ void lds128(uint32_t addr, uint32_t* r) {
    asm volatile("ld.shared.v4.b32 {%0,%1,%2,%3}, [%4];"
                 : "=r"(r[0]), "=r"(r[1]), "=r"(r[2]), "=r"(r[3]) : "r"(addr));
}
__device__ __forceinline__ void lds64(uint32_t addr, uint32_t* r) {
    asm volatile("ld.shared.v2.b32 {%0,%1}, [%2];"
                 : "=r"(r[0]), "=r"(r[1]) : "r"(addr));
}
__device__ __forceinline__ void mma_s8(int* d, const uint32_t* a, const uint32_t* b) {
    asm volatile("mma.sync.aligned.m16n8k32.row.col.s32.s8.s8.s32 "
                 "{%0,%1,%2,%3}, {%4,%5,%6,%7}, {%8,%9}, {%0,%1,%2,%3};"
                 : "+r"(d[0]), "+r"(d[1]), "+r"(d[2]), "+r"(d[3])
                 : "r"(a[0]), "r"(a[1]), "r"(a[2]), "r"(a[3]), "r"(b[0]), "r"(b[1]));
}

// two-limb quantize: iv in [-16256-1, 16256+1]; a = 128*l0 + l1
__device__ __forceinline__ void quant2(float x, float inv, int& l0, int& l1) {
    const int iv = __float2int_rn(x * inv);
    l0 = (iv + 64) >> 7;
    l1 = iv - (l0 << 7);
}
__device__ __forceinline__ uint32_t pk4(int b0, int b1, int b2, int b3) {
    return (uint32_t)(b0 & 255) | ((uint32_t)(b1 & 255) << 8)
         | ((uint32_t)(b2 & 255) << 16) | ((uint32_t)(b3 & 255) << 24);
}
__device__ __forceinline__ void qf4(float4 v, float inv, uint32_t& p0, uint32_t& p1) {
    int a0, a1, b0, b1, c0, c1, d0, d1;
    quant2(v.x, inv, a0, a1); quant2(v.y, inv, b0, b1);
    quant2(v.z, inv, c0, c1); quant2(v.w, inv, d0, d1);
    p0 = pk4(a0, b0, c0, d0);
    p1 = pk4(a1, b1, c1, d1);
}

// ---------------------------------------------------------------------------
// int8 two-limb GEMM: C[M,N](f32) = A @ B^T, operands packed in fragment order.
// CTA tile 128x64, K-chunk 32, 8 warps, warp tile 32x32 (2m x 4n atoms).
// Per k32: 3 mma per atom (a0b0 -> p0 ; a0b1 + a1b0 -> pm).
// C = sa[r]*sb[c]*(16384*p0 + 128*pm).
// ---------------------------------------------------------------------------
#define CTM 128
#define CTN 64
#define SA0 0
#define SA1 4096
#define SB0 8192
#define SB1 10240
#define STAGE_I8 12288
#define SMEM_GI8 (3 * STAGE_I8)   // 36864

__global__ __launch_bounds__(256, 2)
void gemm_i8(const uint8_t* __restrict__ A0, const uint8_t* __restrict__ A1,
             const uint8_t* __restrict__ B0, const uint8_t* __restrict__ B1,
             const float* __restrict__ sa, float sac, const float* __restrict__ sb,
             float* __restrict__ C, int M, int N, int K) {
    extern __shared__ char smem[];
    const uint32_t sbm = smem_to_u32(smem);
    const int tid = threadIdx.x;
    const int wid = tid >> 5;
    const int lane = tid & 31;
    const int row0 = blockIdx.y << 7;
    const int col0 = blockIdx.x << 6;
    const int kbT = K >> 5;
    const int mb0 = row0 >> 4;
    const int nb0 = col0 >> 3;

    const int wm = wid & 3;
    const int wn = wid >> 2;

    auto load_stage = [&](int buf, int kb) {
        const uint32_t st = sbm + buf * STAGE_I8;
        {   // A: 8 atoms x 512B per limb; thread -> one 16B chunk per limb
            const int a = tid >> 5;
            const int inner = (tid & 31) << 4;
            const size_t g = ((size_t)(mb0 + a) * kbT + kb) * 512 + inner;
            cp16(st + SA0 + (a << 9) + inner, A0 + g);
            cp16(st + SA1 + (a << 9) + inner, A1 + g);
        }
        {   // B: 8 atoms x 256B per limb = 128 chunks; tid<128 limb0, else limb1
            const int i = tid & 127;
            const int limb = tid >> 7;
            const int a = i >> 4;
            const int inner = (i & 15) << 4;
            const size_t g = ((size_t)(nb0 + a) * kbT + kb) * 256 + inner;
            cp16(st + SB0 + limb * 2048 + (a << 8) + inner, (limb ? B1 : B0) + g);
        }
    };

    int p0[2][4][4], pm[2][4][4];
#pragma unroll
    for (int i = 0; i < 2; i++)
#pragma unroll
        for (int j = 0; j < 4; j++)
#pragma unroll
            for (int q = 0; q < 4; q++) { p0[i][j][q] = 0; pm[i][j][q] = 0; }

    const int KT = kbT;
    load_stage(0, 0); CP_COMMIT();
    load_stage(1, 1); CP_COMMIT();

    const uint32_t la16 = (uint32_t)lane << 4;
    const uint32_t la8  = (uint32_t)lane << 3;

    int cur = 0, nxt2 = 2;
    for (int kt = 0; kt < KT; kt++) {
        CP_WAIT1();
        __syncthreads();
        if (kt + 2 < KT) load_stage(nxt2, kt + 2);
        CP_COMMIT();

        const uint32_t st = sbm + cur * STAGE_I8;
        uint32_t a0f[2][4], a1f[2][4], b0f[4][2], b1f[4][2];
#pragma unroll
        for (int mi = 0; mi < 2; mi++) {
            const uint32_t aa = st + (uint32_t)(((wm << 1) + mi) << 9) + la16;
            lds128(aa + SA0, a0f[mi]);
            lds128(aa + SA1, a1f[mi]);
        }
#pragma unroll
        for (int ni = 0; ni < 4; ni++) {
            const uint32_t ba = st + (uint32_t)(((wn << 2) + ni) << 8) + la8;
            lds64(ba + SB0, b0f[ni]);
            lds64(ba + SB1, b1f[ni]);
        }
#pragma unroll
        for (int mi = 0; mi < 2; mi++)
#pragma unroll
            for (int ni = 0; ni < 4; ni++)
                mma_s8(p0[mi][ni], a0f[mi], b0f[ni]);
#pragma unroll
        for (int mi = 0; mi < 2; mi++)
#pragma unroll
            for (int ni = 0; ni < 4; ni++)
                mma_s8(pm[mi][ni], a0f[mi], b1f[ni]);
#pragma unroll
        for (int mi = 0; mi < 2; mi++)
#pragma unroll
            for (int ni = 0; ni < 4; ni++)
                mma_s8(pm[mi][ni], a1f[mi], b0f[ni]);

        cur  = (cur == 2)  ? 0 : cur + 1;
        nxt2 = (nxt2 == 2) ? 0 : nxt2 + 1;
    }

    // epilogue
    const int gr = lane >> 2;
    const int tg = lane & 3;
#pragma unroll
    for (int mi = 0; mi < 2; mi++) {
        const int r0 = row0 + (wm << 5) + (mi << 4) + gr;
        const float sa0 = sa ? sa[r0] : sac;
        const float sa8 = sa ? sa[r0 + 8] : sac;
#pragma unroll
        for (int ni = 0; ni < 4; ni++) {
            const int c = col0 + (wn << 5) + (ni << 3) + (tg << 1);
            const float2 sbc = *(const float2*)&sb[c];
            const int* q0 = p0[mi][ni];
            const int* qm = pm[mi][ni];
            float v0 = sa0 * sbc.x * fmaf(16384.f, (float)q0[0], 128.f * (float)qm[0]);
            float v1 = sa0 * sbc.y * fmaf(16384.f, (float)q0[1], 128.f * (float)qm[1]);
            float v2 = sa8 * sbc.x * fmaf(16384.f, (float)q0[2], 128.f * (float)qm[2]);
            float v3 = sa8 * sbc.y * fmaf(16384.f, (float)q0[3], 128.f * (float)qm[3]);
            *(float2*)&C[(size_t)r0 * N + c]       = make_float2(v0, v1);
            *(float2*)&C[(size_t)(r0 + 8) * N + c] = make_float2(v2, v3);
        }
    }
}

// ---------------------------------------------------------------------------
// rowmax over x rows (K=512): one warp per row -> step = max/16256
// ---------------------------------------------------------------------------
__global__ __launch_bounds__(256)
void rowmax_x(const float* __restrict__ x, float* __restrict__ sa) {
    const int row = blockIdx.x * 8 + (threadIdx.x >> 5);
    const int lane = threadIdx.x & 31;
    float m = 0.f;
#pragma unroll
    for (int i = 0; i < DIM / 32; i++)
        m = fmaxf(m, fabsf(x[(size_t)row * DIM + lane + 32 * i]));
#pragma unroll
    for (int o = 16; o > 0; o >>= 1)
        m = fmaxf(m, __shfl_xor_sync(0xFFFFFFFF, m, o));
    if (lane == 0) sa[row] = m * (1.f / 16256.f);
}

// colmax over W[K,N] columns -> step = max/16256
__global__ __launch_bounds__(256)
void colmax_w(const float* __restrict__ W, float* __restrict__ sb, int K, int N) {
    __shared__ float red[8][32];
    const int tx = threadIdx.x, ty = threadIdx.y;
    const int col = blockIdx.x * 32 + tx;
    float m = 0.f;
    for (int k = ty; k < K; k += 8)
        m = fmaxf(m, fabsf(W[(size_t)k * N + col]));
    red[ty][tx] = m;
    __syncthreads();
    if (ty == 0) {
        float mm = red[0][tx];
#pragma unroll
        for (int j = 1; j < 8; j++) mm = fmaxf(mm, red[j][tx]);
        sb[col] = mm * (1.f / 16256.f);
    }
}

// ---------------------------------------------------------------------------
// pack x -> two-limb A atoms (thread per atom-lane; 4x float4 reads)
// ---------------------------------------------------------------------------
__global__ __launch_bounds__(256)
void pack_a_i8(const float* __restrict__ src, uint8_t* __restrict__ d0,
               uint8_t* __restrict__ d1, const float* __restrict__ sa, int M, int K) {
    const int t = blockIdx.x * 256 + threadIdx.x;
    const int kbT = K >> 5;
    const int atom = t >> 5;
    if (atom >= (M >> 4) * kbT) return;
    const int lane = t & 31;
    const int mb = atom / kbT, kb = atom % kbT;
    const int g = lane >> 2, tt = lane & 3;
    const int r0 = mb * 16 + g, r1 = r0 + 8;
    const int c0 = kb * 32 + tt * 4;
    const float inv0 = 1.f / sa[r0];
    const float inv1 = 1.f / sa[r1];
    uint4 o0, o1;
    qf4(*(const float4*)(src + (size_t)r0 * K + c0),      inv0, o0.x, o1.x);  // a0
    qf4(*(const float4*)(src + (size_t)r1 * K + c0),      inv1, o0.y, o1.y);  // a1
    qf4(*(const float4*)(src + (size_t)r0 * K + c0 + 16), inv0, o0.z, o1.z);  // a2
    qf4(*(const float4*)(src + (size_t)r1 * K + c0 + 16), inv1, o0.w, o1.w);  // a3
    *(uint4*)(d0 + (size_t)atom * 512 + lane * 16) = o0;
    *(uint4*)(d1 + (size_t)atom * 512 + lane * 16) = o1;
}

// pack W[K,N] -> two-limb B atoms of W^T
__global__ __launch_bounds__(256)
void pack_w_i8(const float* __restrict__ W, uint8_t* __restrict__ d0,
               uint8_t* __restrict__ d1, const float* __restrict__ sb, int K, int N) {
    const int t = blockIdx.x * 256 + threadIdx.x;
    const int kbT = K >> 5;
    const int atom = t >> 5;
    if (atom >= (N >> 3) * kbT) return;
    const int lane = t & 31;
    const int nb = atom / kbT, kb = atom % kbT;
    const int g = lane >> 2, tt = lane & 3;
    const int n = nb * 8 + g;
    const int k0 = kb * 32 + tt * 4;
    const float inv = 1.f / sb[n];
    float4 w0, w1;
    w0.x = W[(size_t)(k0 + 0) * N + n]; w0.y = W[(size_t)(k0 + 1) * N + n];
    w0.z = W[(size_t)(k0 + 2) * N + n]; w0.w = W[(size_t)(k0 + 3) * N + n];
    w1.x = W[(size_t)(k0 + 16) * N + n]; w1.y = W[(size_t)(k0 + 17) * N + n];
    w1.z = W[(size_t)(k0 + 18) * N + n]; w1.w = W[(size_t)(k0 + 19) * N + n];
    uint2 o0, o1;
    qf4(w0, inv, o0.x, o1.x);   // b0
    qf4(w1, inv, o0.y, o1.y);   // b1
    *(uint2*)(d0 + (size_t)atom * 256 + lane * 8) = o0;
    *(uint2*)(d1 + (size_t)atom * 256 + lane * 8) = o1;
}

// ---------------------------------------------------------------------------
// Gaussian banded smoothing (WIN=16), row-normalized; quantizes with fixed
// scale SMAX_S and stages packed limbs in SMEM, then writes coalesced.
// Block: 64 rows x 64 channels  ->  8 A atoms (4 mb x 2 kb) per limb.
// ---------------------------------------------------------------------------
__global__ __launch_bounds__(256)
void smooth_kernel(const float* __restrict__ y, uint8_t* __restrict__ d0,
                   uint8_t* __restrict__ d1, const float* __restrict__ sigma) {
    __shared__ float yt[TN + 2 * WIN][64];
    __shared__ float ew[2 * WIN + 1];
    __shared__ float invZ[TN];
    __shared__ __align__(16) uint8_t stg0[4096];
    __shared__ __align__(16) uint8_t stg1[4096];

    const int n0 = blockIdx.x * TN;
    const int half = blockIdx.y;
    const int bh = blockIdx.z;
    const int b = bh >> 3;
    const int h = bh & 7;
    const int tid = threadIdx.x;

    const float* ybase = y + (size_t)b * NSEQ * INNER + h * DHEAD + half * 64;
    for (int i = tid; i < (TN + 2 * WIN) * 16; i += 256) {
        const int r = i >> 4;
        const int c = (i & 15) << 2;
        const int m = n0 - WIN + r;
        float4 v = make_float4(0.f, 0.f, 0.f, 0.f);
        if (m >= 0 && m < NSEQ) v = *(const float4*)(ybase + (size_t)m * INNER + c);
        *(float4*)&yt[r][c] = v;
    }
    if (tid < 2 * WIN + 1) {
        const float sg = sigma[h];
        const float dd = (float)(tid - WIN);
        ew[tid] = __expf(-dd * dd / (2.f * sg * sg));
    }
    __syncthreads();
    if (tid < TN) {
        const int n = n0 + tid;
        float z = 0.f;
#pragma unroll
        for (int j = 0; j <= 2 * WIN; j++) {
            const int m = n - WIN + j;
            if (m >= 0 && m < NSEQ) z += ew[j];
        }
        invZ[tid] = 1.f / z;
    }
    __syncthreads();

    const int cp = tid & 31;     // channel pair 0..31
    const int tg = tid >> 5;     // 0..7
    const float qinv = 16256.f / SMAX_S;
    // fragment indexing for channels: kc = (2*cp)&31, kbL = cp>>4
    const int kc  = (2 * cp) & 31;
    const int kbL = cp >> 4;
    const int fr_lane = (kc & 15) >> 2;       // column part of lane id
    const int reg_k   = (kc >> 4) << 1;       // selects a2/a3 when kc>=16
#pragma unroll
    for (int k = 0; k < 8; k++) {
        const int t = tg * 8 + k;
        ull acc = 0ULL;
#pragma unroll
        for (int j = 0; j <= 2 * WIN; j++) {
            const ull w = pack_dup(ew[j]);
            const ull v = *(const ull*)&yt[t + j][cp << 1];
            ffma2(acc, w, v);
        }
        float ax, ay;
        unpack2(acc, ax, ay);
        const float iz = invZ[t];
        int iv0 = __float2int_rn(ax * iz * qinv);
        int iv1 = __float2int_rn(ay * iz * qinv);
        iv0 = max(min(iv0, 16256), -16256);
        iv1 = max(min(iv1, 16256), -16256);
        const int l00 = (iv0 + 64) >> 7, l01 = iv0 - (l00 << 7);
        const int l10 = (iv1 + 64) >> 7, l11 = iv1 - (l10 << 7);
        // stage into packed atom layout
        const int mbL = t >> 4;
        const int r16 = t & 15;
        const int atomL = mbL * 2 + kbL;
        const int lanef = ((r16 & 7) << 2) + fr_lane;
        const int regi  = reg_k + (r16 >> 3);            // [a0,a1,a2,a3]
        const int off = atomL * 512 + lanef * 16 + regi * 4 + (kc & 3);
        *(uint16_t*)(stg0 + off) = (uint16_t)((l00 & 255) | ((l10 & 255) << 8));
        *(uint16_t*)(stg1 + off) = (uint16_t)((l01 & 255) | ((l11 & 255) << 8));
    }
    __syncthreads();

    // coalesced writeout: 256 chunks of 16B per limb
    const int mbG0 = (b * NSEQ + n0) >> 4;
    const int kbG0 = h * 4 + half * 2;
    {
        const int c = tid;
        const int atomL = c >> 5;
        const int inner = (c & 31) << 4;
        const int mbL = atomL >> 1, kbL2 = atomL & 1;
        const size_t atomG = ((size_t)(mbG0 + mbL) * (INNER / 32) + kbG0 + kbL2);
        *(uint4*)(d0 + atomG * 512 + inner) = *(uint4*)(stg0 + atomL * 512 + inner);
        *(uint4*)(d1 + atomG * 512 + inner) = *(uint4*)(stg1 + atomL * 512 + inner);
    }
}

// ---------------------------------------------------------------------------
extern "C" void kernel_launch(void* const* d_in, const int* in_sizes, int n_in,
                              void* d_out, int out_size) {
    const float* x     = (const float*)d_in[0];
    const float* Wg    = (const float*)d_in[1];
    const float* Wout  = (const float*)d_in[2];
    const float* sigma = (const float*)d_in[3];
    float* out = (float*)d_out;

    float *y, *sax, *sb1, *sb2;
    uint8_t *x0, *x1, *s0, *s1, *w10, *w11, *w20, *w21;
    cudaGetSymbolAddress((void**)&y,   g_y);
    cudaGetSymbolAddress((void**)&x0,  g_x0);  cudaGetSymbolAddress((void**)&x1,  g_x1);
    cudaGetSymbolAddress((void**)&s0,  g_s0);  cudaGetSymbolAddress((void**)&s1,  g_s1);
    cudaGetSymbolAddress((void**)&w10, g_w10); cudaGetSymbolAddress((void**)&w11, g_w11);
    cudaGetSymbolAddress((void**)&w20, g_w20); cudaGetSymbolAddress((void**)&w21, g_w21);
    cudaGetSymbolAddress((void**)&sax, g_sax);
    cudaGetSymbolAddress((void**)&sb1, g_sb1);
    cudaGetSymbolAddress((void**)&sb2, g_sb2);

    cudaFuncSetAttribute(gemm_i8, cudaFuncAttributeMaxDynamicSharedMemorySize, SMEM_GI8);

    // scales
    rowmax_x<<<MROWS / 8, 256>>>(x, sax);
    colmax_w<<<INNER / 32, dim3(32, 8)>>>(Wg, sb1, DIM, INNER);
    colmax_w<<<DIM / 32, dim3(32, 8)>>>(Wout, sb2, INNER, DIM);

    // packs
    pack_a_i8<<<(MROWS / 16) * (DIM / 32) * 32 / 256, 256>>>(x, x0, x1, sax, MROWS, DIM);
    pack_w_i8<<<(INNER / 8) * (DIM / 32) * 32 / 256, 256>>>(Wg, w10, w11, sb1, DIM, INNER);
    pack_w_i8<<<(DIM / 8) * (INNER / 32) * 32 / 256, 256>>>(Wout, w20, w21, sb2, INNER, DIM);

    // GEMM1: y = x @ Wg
    gemm_i8<<<dim3(INNER / CTN, MROWS / CTM), 256, SMEM_GI8>>>(
        x0, x1, w10, w11, sax, 0.f, sb1, y, MROWS, INNER, DIM);

    // banded Gaussian attention -> packed int8 limbs
    smooth_kernel<<<dim3(NSEQ / TN, 2, BATCH * NHEAD), 256>>>(y, s0, s1, sigma);

    // GEMM2: out = s @ Wout  (fixed A scale)
    gemm_i8<<<dim3(DIM / CTN, MROWS / CTM), 256, SMEM_GI8>>>(
        s0, s1, w20, w21, nullptr, SMAX_S / 16256.f, sb2, out, MROWS, DIM, INNER);
}

// round 10
// speedup vs baseline: 4.6892x; 4.6892x over previous
#include <cuda_runtime.h>
#include <cuda_fp16.h>
#include <cstdint>
#include <cstddef>

// Problem constants
#define BATCH 4
#define NSEQ 2048
#define DIM 512
#define NHEAD 8
#define DHEAD 128
#define INNER 1024
#define MROWS (BATCH*NSEQ)  // 8192

#define WIN 16
#define TN 64

// ---------------- scratch (allocation-free rule) ----------------
// fp16 packed operands in m16n8k16 fragment order.
// A atom = 16x16 f16 = 512B: lane*16 -> [a0,a1,a2,a3] (each b32 = 2 f16).
// B atom = 8x16  f16 = 256B: lane*8  -> [b0,b1].
__device__ __align__(16) float  g_y[MROWS * INNER];
__device__ __align__(16) __half g_xpk[MROWS * DIM];
__device__ __align__(16) __half g_spk[MROWS * INNER];
__device__ __align__(16) __half g_wgpk[DIM * INNER];    // Wg^T packed
__device__ __align__(16) __half g_wopk[INNER * DIM];    // Wout^T packed

// ---------------- helpers ----------------
typedef unsigned long long ull;
__device__ __forceinline__ ull pack_dup(float a) {
    ull r; asm("mov.b64 %0, {%1, %1};" : "=l"(r) : "f"(a)); return r;
}
__device__ __forceinline__ void ffma2(ull& d, ull a, ull b) {
    asm("fma.rn.f32x2 %0, %1, %2, %0;" : "+l"(d) : "l"(a), "l"(b));
}
__device__ __forceinline__ void unpack2(ull v, float& lo, float& hi) {
    asm("mov.b64 {%0, %1}, %2;" : "=f"(lo), "=f"(hi) : "l"(v));
}
__device__ __forceinline__ uint32_t smem_to_u32(const void* p) {
    uint32_t a;
    asm("{ .reg .u64 t; cvta.to.shared.u64 t, %1; cvt.u32.u64 %0, t; }" : "=r"(a) : "l"(p));
    return a;
}
__device__ __forceinline__ void cp16(uint32_t dst, const void* src) {
    asm volatile("cp.async.cg.shared.global [%0], [%1], 16;" :: "r"(dst), "l"(src) : "memory");
}
#define CP_COMMIT() asm volatile("cp.async.commit_group;" ::: "memory")
#define CP_WAIT1()  asm volatile("cp.async.wait_group 1;" ::: "memory")

__device__ __forceinline__ void lds128(uint32_t addr, uint32_t* r) {
    asm volatile("ld.shared.v4.b32 {%0,%1,%2,%3}, [%4];"
                 : "=r"(r[0]), "=r"(r[1]), "=r"(r[2]), "=r"(r[3]) : "r"(addr));
}
__device__ __forceinline__ void lds64(uint32_t addr, uint32_t* r) {
    asm volatile("ld.shared.v2.b32 {%0,%1}, [%2];"
                 : "=r"(r[0]), "=r"(r[1]) : "r"(addr));
}
__device__ __forceinline__ void mma_f16(float* d, const uint32_t* a, const uint32_t* b) {
    asm volatile("mma.sync.aligned.m16n8k16.row.col.f32.f16.f16.f32 "
                 "{%0,%1,%2,%3}, {%4,%5,%6,%7}, {%8,%9}, {%0,%1,%2,%3};"
                 : "+f"(d[0]), "+f"(d[1]), "+f"(d[2]), "+f"(d[3])
                 : "r"(a[0]), "r"(a[1]), "r"(a[2]), "r"(a[3]), "r"(b[0]), "r"(b[1]));
}
__device__ __forceinline__ uint32_t h2u(float a, float b) {
    __half2 h = __floats2half2_rn(a, b);
    return *(uint32_t*)&h;
}

// ---------------------------------------------------------------------------
// fp16 GEMM: C[M,N](f32) = A[M,K] @ B^T, operands pre-packed in fragment order.
// CTA tile 128x64, K-chunk 32 (2 k16 atoms), 8 warps, warp tile 32x32.
// 3-stage cp.async pipeline; fragment loads: LDS.128 (A), LDS.64 (B).
// ---------------------------------------------------------------------------
#define CTM 128
#define CTN 64
#define STG_A_BYTES 8192       // 16 A atoms (8 mb x 2 kb) x 512B
#define STG_B_BYTES 4096       // 16 B atoms (8 nb x 2 kb) x 256B
#define STAGE_BYTES (STG_A_BYTES + STG_B_BYTES)  // 12288
#define SMEM_GEMM (3 * STAGE_BYTES)              // 36864

__global__ __launch_bounds__(256, 2)
void gemm_f16(const __half* __restrict__ Apk, const __half* __restrict__ Bpk,
              float* __restrict__ C, int M, int N, int K) {
    extern __shared__ char smem[];
    const uint32_t sb = smem_to_u32(smem);
    const int tid = threadIdx.x;
    const int wid = tid >> 5;
    const int lane = tid & 31;
    const int row0 = blockIdx.y << 7;
    const int col0 = blockIdx.x << 6;
    const int kbT = K >> 4;             // k16 blocks total
    const int mb0 = row0 >> 4;
    const int nb0 = col0 >> 3;

    const int wm = wid & 3;             // 2 m-blocks each
    const int wn = wid >> 2;            // 4 n-blocks each

    auto load_stage = [&](int buf, int kt) {
        const uint32_t st = sb + buf * STAGE_BYTES;
        const int kb0 = kt << 1;
        // A: 16 atoms x 32 chunks = 512 chunks of 16B
#pragma unroll
        for (int r = 0; r < 2; r++) {
            const int i = tid + (r << 8);
            const int atomL = i >> 5;               // 0..15
            const int inner = (i & 31) << 4;
            const int mbL = atomL >> 1, kbL = atomL & 1;
            const size_t g = ((size_t)(mb0 + mbL) * kbT + kb0 + kbL) * 512 + inner;
            cp16(st + (atomL << 9) + inner, (const char*)Apk + g);
        }
        // B: 16 atoms x 16 chunks = 256 chunks
        {
            const int atomL = tid >> 4;
            const int inner = (tid & 15) << 4;
            const int nbL = atomL >> 1, kbL = atomL & 1;
            const size_t g = ((size_t)(nb0 + nbL) * kbT + kb0 + kbL) * 256 + inner;
            cp16(st + STG_A_BYTES + (atomL << 8) + inner, (const char*)Bpk + g);
        }
    };

    float d[2][4][4];
#pragma unroll
    for (int i = 0; i < 2; i++)
#pragma unroll
        for (int j = 0; j < 4; j++)
#pragma unroll
            for (int q = 0; q < 4; q++) d[i][j][q] = 0.f;

    const int KT = K >> 5;              // 32-k chunks
    load_stage(0, 0); CP_COMMIT();
    load_stage(1, 1); CP_COMMIT();

    const uint32_t la16 = (uint32_t)lane << 4;
    const uint32_t la8  = (uint32_t)lane << 3;

    int cur = 0, nxt2 = 2;
    for (int kt = 0; kt < KT; kt++) {
        CP_WAIT1();
        __syncthreads();
        if (kt + 2 < KT) load_stage(nxt2, kt + 2);
        CP_COMMIT();

        const uint32_t st = sb + cur * STAGE_BYTES;
#pragma unroll
        for (int ki = 0; ki < 2; ki++) {
            uint32_t a[2][4], b[4][2];
#pragma unroll
            for (int mi = 0; mi < 2; mi++)
                lds128(st + (uint32_t)(((((wm << 1) + mi) << 1) + ki) << 9) + la16, a[mi]);
#pragma unroll
            for (int ni = 0; ni < 4; ni++)
                lds64(st + STG_A_BYTES
                      + (uint32_t)(((((wn << 2) + ni) << 1) + ki) << 8) + la8, b[ni]);
#pragma unroll
            for (int mi = 0; mi < 2; mi++)
#pragma unroll
                for (int ni = 0; ni < 4; ni++)
                    mma_f16(d[mi][ni], a[mi], b[ni]);
        }
        cur  = (cur == 2)  ? 0 : cur + 1;
        nxt2 = (nxt2 == 2) ? 0 : nxt2 + 1;
    }

    // epilogue: atom (mi, ni) -> rows (g, g+8), cols (tg*2, +1)
    const int gr = lane >> 2;
    const int tg = lane & 3;
#pragma unroll
    for (int mi = 0; mi < 2; mi++) {
        const int r0 = row0 + (wm << 5) + (mi << 4) + gr;
#pragma unroll
        for (int ni = 0; ni < 4; ni++) {
            const int c = col0 + (wn << 5) + (ni << 3) + (tg << 1);
            *(float2*)&C[(size_t)r0 * N + c]       = make_float2(d[mi][ni][0], d[mi][ni][1]);
            *(float2*)&C[(size_t)(r0 + 8) * N + c] = make_float2(d[mi][ni][2], d[mi][ni][3]);
        }
    }
}

// ---------------------------------------------------------------------------
// pack_a: row-major [M,K] f32 -> packed f16 A atoms (16x16, fragment order)
// lane (g,tt): a0=(g,2tt..+1), a1=(g+8,..), a2=(g,2tt+8..), a3=(g+8,..)
// ---------------------------------------------------------------------------
__global__ __launch_bounds__(256)
void pack_a_f16(const float* __restrict__ src, __half* __restrict__ dst, int M, int K) {
    const int t = blockIdx.x * 256 + threadIdx.x;
    const int kbT = K >> 4;
    const int atom = t >> 5;
    if (atom >= (M >> 4) * kbT) return;
    const int lane = t & 31;
    const int mb = atom / kbT, kb = atom % kbT;
    const int g = lane >> 2, tt = lane & 3;
    const int r0 = mb * 16 + g, r1 = r0 + 8;
    const int c0 = kb * 16 + tt * 2;
    const float2 v0 = *(const float2*)(src + (size_t)r0 * K + c0);
    const float2 v1 = *(const float2*)(src + (size_t)r1 * K + c0);
    const float2 v2 = *(const float2*)(src + (size_t)r0 * K + c0 + 8);
    const float2 v3 = *(const float2*)(src + (size_t)r1 * K + c0 + 8);
    uint4 o;
    o.x = h2u(v0.x, v0.y);
    o.y = h2u(v1.x, v1.y);
    o.z = h2u(v2.x, v2.y);
    o.w = h2u(v3.x, v3.y);
    *(uint4*)((char*)dst + (size_t)atom * 512 + lane * 16) = o;
}

// ---------------------------------------------------------------------------
// pack_w: W[K,N] f32 -> packed f16 B atoms of W^T (8x16 fragment order)
// lane (g,tt): b0=(k=2tt..+1, n=g), b1=(k=2tt+8..+9, n=g)
// ---------------------------------------------------------------------------
__global__ __launch_bounds__(256)
void pack_w_f16(const float* __restrict__ W, __half* __restrict__ dst, int K, int N) {
    const int t = blockIdx.x * 256 + threadIdx.x;
    const int kbT = K >> 4;
    const int atom = t >> 5;
    if (atom >= (N >> 3) * kbT) return;
    const int lane = t & 31;
    const int nb = atom / kbT, kb = atom % kbT;
    const int g = lane >> 2, tt = lane & 3;
    const int n = nb * 8 + g;
    const int k0 = kb * 16 + tt * 2;
    uint2 o;
    o.x = h2u(W[(size_t)k0 * N + n],       W[(size_t)(k0 + 1) * N + n]);
    o.y = h2u(W[(size_t)(k0 + 8) * N + n], W[(size_t)(k0 + 9) * N + n]);
    *(uint2*)((char*)dst + (size_t)atom * 256 + lane * 8) = o;
}

// ---------------------------------------------------------------------------
// Gaussian banded smoothing (WIN=16), row-normalized, f32x2 packed math;
// writes s directly in packed fp16 A-fragment layout (one b32 per row/ch-pair).
// ---------------------------------------------------------------------------
__global__ __launch_bounds__(256)
void smooth_kernel(const float* __restrict__ y, __half* __restrict__ spk,
                   const float* __restrict__ sigma) {
    __shared__ float yt[TN + 2 * WIN][64];
    __shared__ float ew[2 * WIN + 1];
    __shared__ float invZ[TN];

    const int n0 = blockIdx.x * TN;
    const int half = blockIdx.y;
    const int bh = blockIdx.z;
    const int b = bh >> 3;
    const int h = bh & 7;
    const int tid = threadIdx.x;

    const float* ybase = y + (size_t)b * NSEQ * INNER + h * DHEAD + half * 64;
    for (int i = tid; i < (TN + 2 * WIN) * 16; i += 256) {
        const int r = i >> 4;
        const int c = (i & 15) << 2;
        const int m = n0 - WIN + r;
        float4 v = make_float4(0.f, 0.f, 0.f, 0.f);
        if (m >= 0 && m < NSEQ) v = *(const float4*)(ybase + (size_t)m * INNER + c);
        *(float4*)&yt[r][c] = v;
    }
    if (tid < 2 * WIN + 1) {
        const float sg = sigma[h];
        const float dd = (float)(tid - WIN);
        ew[tid] = __expf(-dd * dd / (2.f * sg * sg));
    }
    __syncthreads();
    if (tid < TN) {
        const int n = n0 + tid;
        float z = 0.f;
#pragma unroll
        for (int j = 0; j <= 2 * WIN; j++) {
            const int m = n - WIN + j;
            if (m >= 0 && m < NSEQ) z += ew[j];
        }
        invZ[tid] = 1.f / z;
    }
    __syncthreads();

    const int cp = tid & 31;     // channel pair
    const int tg = tid >> 5;     // 0..7
    const int c0 = h * DHEAD + half * 64 + (cp << 1);   // even channel
    const int kbG = c0 >> 4;
    const int k16 = c0 & 15;                             // even
    const int tt = (k16 >> 1) & 3;
    const int khalf = k16 >> 3;
#pragma unroll
    for (int k = 0; k < 8; k++) {
        const int t = tg * 8 + k;
        ull acc = 0ULL;
#pragma unroll
        for (int j = 0; j <= 2 * WIN; j++) {
            const ull w = pack_dup(ew[j]);
            const ull v = *(const ull*)&yt[t + j][cp << 1];
            ffma2(acc, w, v);
        }
        float ax, ay;
        unpack2(acc, ax, ay);
        const float iz = invZ[t];
        const uint32_t pr = h2u(ax * iz, ay * iz);
        const int m = b * NSEQ + n0 + t;
        const int mb = m >> 4;
        const int r16 = m & 15;
        const int g = r16 & 7;
        const int up = r16 >> 3;
        const int lanef = (g << 2) + tt;
        const int reg = (khalf << 1) + up;
        const size_t off = ((size_t)mb * (INNER / 16) + kbG) * 512 + lanef * 16 + reg * 4;
        *(uint32_t*)((char*)spk + off) = pr;
    }
}

// ---------------------------------------------------------------------------
extern "C" void kernel_launch(void* const* d_in, const int* in_sizes, int n_in,
                              void* d_out, int out_size) {
    const float* x     = (const float*)d_in[0];
    const float* Wg    = (const float*)d_in[1];
    const float* Wout  = (const float*)d_in[2];
    const float* sigma = (const float*)d_in[3];
    float* out = (float*)d_out;

    float* y; __half *xpk, *spk, *wgpk, *wopk;
    cudaGetSymbolAddress((void**)&y,    g_y);
    cudaGetSymbolAddress((void**)&xpk,  g_xpk);
    cudaGetSymbolAddress((void**)&spk,  g_spk);
    cudaGetSymbolAddress((void**)&wgpk, g_wgpk);
    cudaGetSymbolAddress((void**)&wopk, g_wopk);

    cudaFuncSetAttribute(gemm_f16, cudaFuncAttributeMaxDynamicSharedMemorySize, SMEM_GEMM);

    // prep: pack x, Wg^T, Wout^T to fp16 fragment layouts
    pack_a_f16<<<(MROWS / 16) * (DIM / 16) * 32 / 256, 256>>>(x, xpk, MROWS, DIM);
    pack_w_f16<<<(INNER / 8) * (DIM / 16) * 32 / 256, 256>>>(Wg, wgpk, DIM, INNER);
    pack_w_f16<<<(DIM / 8) * (INNER / 16) * 32 / 256, 256>>>(Wout, wopk, INNER, DIM);

    // GEMM1: y[8192,1024] = x @ Wg
    gemm_f16<<<dim3(INNER / CTN, MROWS / CTM), 256, SMEM_GEMM>>>(
        xpk, wgpk, y, MROWS, INNER, DIM);

    // banded Gaussian attention -> s (packed fp16)
    smooth_kernel<<<dim3(NSEQ / TN, 2, BATCH * NHEAD), 256>>>(y, spk, sigma);

    // GEMM2: out[8192,512] = s @ Wout
    gemm_f16<<<dim3(DIM / CTN, MROWS / CTM), 256, SMEM_GEMM>>>(
        spk, wopk, out, MROWS, DIM, INNER);
}

// round 11
// speedup vs baseline: 4.8937x; 1.0436x over previous
#include <cuda_runtime.h>
#include <cuda_fp16.h>
#include <cstdint>
#include <cstddef>

// Problem constants
#define BATCH 4
#define NSEQ 2048
#define DIM 512
#define NHEAD 8
#define DHEAD 128
#define INNER 1024
#define MROWS (BATCH*NSEQ)  // 8192

#define WIN 16
#define TN 64

// ---------------- scratch (allocation-free rule) ----------------
// fp16 packed operands in m16n8k16 fragment order.
// A atom = 16x16 f16 = 512B: lane*16 -> [a0,a1,a2,a3] (each b32 = 2 f16).
// B atom = 8x16  f16 = 256B: lane*8  -> [b0,b1].
__device__ __align__(16) __half g_y[MROWS * INNER];     // gemm1 out, fp16 row-major
__device__ __align__(16) __half g_xpk[MROWS * DIM];
__device__ __align__(16) __half g_spk[MROWS * INNER];
__device__ __align__(16) __half g_wgpk[DIM * INNER];    // Wg^T packed
__device__ __align__(16) __half g_wopk[INNER * DIM];    // Wout^T packed

// ---------------- helpers ----------------
typedef unsigned long long ull;
__device__ __forceinline__ ull pack_dup(float a) {
    ull r; asm("mov.b64 %0, {%1, %1};" : "=l"(r) : "f"(a)); return r;
}
__device__ __forceinline__ void ffma2(ull& d, ull a, ull b) {
    asm("fma.rn.f32x2 %0, %1, %2, %0;" : "+l"(d) : "l"(a), "l"(b));
}
__device__ __forceinline__ void unpack2(ull v, float& lo, float& hi) {
    asm("mov.b64 {%0, %1}, %2;" : "=f"(lo), "=f"(hi) : "l"(v));
}
__device__ __forceinline__ uint32_t smem_to_u32(const void* p) {
    uint32_t a;
    asm("{ .reg .u64 t; cvta.to.shared.u64 t, %1; cvt.u32.u64 %0, t; }" : "=r"(a) : "l"(p));
    return a;
}
__device__ __forceinline__ void cp16(uint32_t dst, const void* src) {
    asm volatile("cp.async.cg.shared.global [%0], [%1], 16;" :: "r"(dst), "l"(src) : "memory");
}
#define CP_COMMIT() asm volatile("cp.async.commit_group;" ::: "memory")
#define CP_WAIT1()  asm volatile("cp.async.wait_group 1;" ::: "memory")

__device__ __forceinline__ void lds128(uint32_t addr, uint32_t* r) {
    asm volatile("ld.shared.v4.b32 {%0,%1,%2,%3}, [%4];"
                 : "=r"(r[0]), "=r"(r[1]), "=r"(r[2]), "=r"(r[3]) : "r"(addr));
}
__device__ __forceinline__ void lds64(uint32_t addr, uint32_t* r) {
    asm volatile("ld.shared.v2.b32 {%0,%1}, [%2];"
                 : "=r"(r[0]), "=r"(r[1]) : "r"(addr));
}
__device__ __forceinline__ void mma_f16(float* d, const uint32_t* a, const uint32_t* b) {
    asm volatile("mma.sync.aligned.m16n8k16.row.col.f32.f16.f16.f32 "
                 "{%0,%1,%2,%3}, {%4,%5,%6,%7}, {%8,%9}, {%0,%1,%2,%3};"
                 : "+f"(d[0]), "+f"(d[1]), "+f"(d[2]), "+f"(d[3])
                 : "r"(a[0]), "r"(a[1]), "r"(a[2]), "r"(a[3]), "r"(b[0]), "r"(b[1]));
}
__device__ __forceinline__ uint32_t h2u(float a, float b) {
    __half2 h = __floats2half2_rn(a, b);
    return *(uint32_t*)&h;
}

// ---------------------------------------------------------------------------
// fp16 GEMM: C[M,N] = A[M,K] @ B^T, operands pre-packed in fragment order.
// CTA tile 128x128, K-chunk 32 (2 k16), 8 warps (2m x 4n), warp tile 64x32.
// 3-stage cp.async pipeline. C written f32 or f16 (halfOut).
// ---------------------------------------------------------------------------
#define CTM 128
#define CTN 128
#define STG_A_BYTES 8192       // 16 A atoms (8 mb x 2 kb) x 512B
#define STG_B_BYTES 8192       // 32 B atoms (16 nb x 2 kb) x 256B
#define STAGE_BYTES (STG_A_BYTES + STG_B_BYTES)  // 16384
#define SMEM_GEMM (3 * STAGE_BYTES)              // 49152

__global__ __launch_bounds__(256, 2)
void gemm_f16(const __half* __restrict__ Apk, const __half* __restrict__ Bpk,
              void* __restrict__ Cv, int halfOut, int M, int N, int K) {
    extern __shared__ char smem[];
    const uint32_t sb = smem_to_u32(smem);
    const int tid = threadIdx.x;
    const int wid = tid >> 5;
    const int lane = tid & 31;
    const int row0 = blockIdx.y << 7;
    const int col0 = blockIdx.x << 7;
    const int kbT = K >> 4;
    const int mb0 = row0 >> 4;
    const int nb0 = col0 >> 3;

    const int wm = wid & 1;             // 4 m-blocks (64 rows)
    const int wn = wid >> 1;            // 4 n-blocks (32 cols)

    auto load_stage = [&](int buf, int kt) {
        const uint32_t st = sb + buf * STAGE_BYTES;
        const int kb0 = kt << 1;
        // A: 16 atoms x 512B = 512 chunks of 16B
#pragma unroll
        for (int r = 0; r < 2; r++) {
            const int i = tid + (r << 8);
            const int atomL = i >> 5;
            const int inner = (i & 31) << 4;
            const int mbL = atomL >> 1, kbL = atomL & 1;
            const size_t g = ((size_t)(mb0 + mbL) * kbT + kb0 + kbL) * 512 + inner;
            cp16(st + (atomL << 9) + inner, (const char*)Apk + g);
        }
        // B: 32 atoms x 256B = 512 chunks
#pragma unroll
        for (int r = 0; r < 2; r++) {
            const int i = tid + (r << 8);
            const int atomL = i >> 4;
            const int inner = (i & 15) << 4;
            const int nbL = atomL >> 1, kbL = atomL & 1;
            const size_t g = ((size_t)(nb0 + nbL) * kbT + kb0 + kbL) * 256 + inner;
            cp16(st + STG_A_BYTES + (atomL << 8) + inner, (const char*)Bpk + g);
        }
    };

    float d[4][4][4];
#pragma unroll
    for (int i = 0; i < 4; i++)
#pragma unroll
        for (int j = 0; j < 4; j++)
#pragma unroll
            for (int q = 0; q < 4; q++) d[i][j][q] = 0.f;

    const int KT = K >> 5;
    load_stage(0, 0); CP_COMMIT();
    load_stage(1, 1); CP_COMMIT();

    const uint32_t la16 = (uint32_t)lane << 4;
    const uint32_t la8  = (uint32_t)lane << 3;

    int cur = 0, nxt2 = 2;
    for (int kt = 0; kt < KT; kt++) {
        CP_WAIT1();
        __syncthreads();
        if (kt + 2 < KT) load_stage(nxt2, kt + 2);
        CP_COMMIT();

        const uint32_t st = sb + cur * STAGE_BYTES;
#pragma unroll
        for (int ki = 0; ki < 2; ki++) {
            uint32_t a[4][4], b[4][2];
#pragma unroll
            for (int mi = 0; mi < 4; mi++)
                lds128(st + (uint32_t)(((((wm << 2) + mi) << 1) + ki) << 9) + la16, a[mi]);
#pragma unroll
            for (int ni = 0; ni < 4; ni++)
                lds64(st + STG_A_BYTES
                      + (uint32_t)(((((wn << 2) + ni) << 1) + ki) << 8) + la8, b[ni]);
#pragma unroll
            for (int mi = 0; mi < 4; mi++)
#pragma unroll
                for (int ni = 0; ni < 4; ni++)
                    mma_f16(d[mi][ni], a[mi], b[ni]);
        }
        cur  = (cur == 2)  ? 0 : cur + 1;
        nxt2 = (nxt2 == 2) ? 0 : nxt2 + 1;
    }

    // epilogue: atom (mi, ni) -> rows (g, g+8), cols (tg*2, +1)
    const int gr = lane >> 2;
    const int tg = lane & 3;
    if (halfOut) {
        __half* C = (__half*)Cv;
#pragma unroll
        for (int mi = 0; mi < 4; mi++) {
            const int r0 = row0 + (wm << 6) + (mi << 4) + gr;
#pragma unroll
            for (int ni = 0; ni < 4; ni++) {
                const int c = col0 + (wn << 5) + (ni << 3) + (tg << 1);
                *(uint32_t*)&C[(size_t)r0 * N + c]       = h2u(d[mi][ni][0], d[mi][ni][1]);
                *(uint32_t*)&C[(size_t)(r0 + 8) * N + c] = h2u(d[mi][ni][2], d[mi][ni][3]);
            }
        }
    } else {
        float* C = (float*)Cv;
#pragma unroll
        for (int mi = 0; mi < 4; mi++) {
            const int r0 = row0 + (wm << 6) + (mi << 4) + gr;
#pragma unroll
            for (int ni = 0; ni < 4; ni++) {
                const int c = col0 + (wn << 5) + (ni << 3) + (tg << 1);
                *(float2*)&C[(size_t)r0 * N + c]       = make_float2(d[mi][ni][0], d[mi][ni][1]);
                *(float2*)&C[(size_t)(r0 + 8) * N + c] = make_float2(d[mi][ni][2], d[mi][ni][3]);
            }
        }
    }
}

// ---------------------------------------------------------------------------
// pack_a: row-major [M,K] f32 -> packed f16 A atoms (16x16, fragment order)
// ---------------------------------------------------------------------------
__global__ __launch_bounds__(256)
void pack_a_f16(const float* __restrict__ src, __half* __restrict__ dst, int M, int K) {
    const int t = blockIdx.x * 256 + threadIdx.x;
    const int kbT = K >> 4;
    const int atom = t >> 5;
    if (atom >= (M >> 4) * kbT) return;
    const int lane = t & 31;
    const int mb = atom / kbT, kb = atom % kbT;
    const int g = lane >> 2, tt = lane & 3;
    const int r0 = mb * 16 + g, r1 = r0 + 8;
    const int c0 = kb * 16 + tt * 2;
    const float2 v0 = *(const float2*)(src + (size_t)r0 * K + c0);
    const float2 v1 = *(const float2*)(src + (size_t)r1 * K + c0);
    const float2 v2 = *(const float2*)(src + (size_t)r0 * K + c0 + 8);
    const float2 v3 = *(const float2*)(src + (size_t)r1 * K + c0 + 8);
    uint4 o;
    o.x = h2u(v0.x, v0.y);
    o.y = h2u(v1.x, v1.y);
    o.z = h2u(v2.x, v2.y);
    o.w = h2u(v3.x, v3.y);
    *(uint4*)((char*)dst + (size_t)atom * 512 + lane * 16) = o;
}

// ---------------------------------------------------------------------------
// pack_w: W[K,N] f32 -> packed f16 B atoms of W^T (8x16 fragment order)
// ---------------------------------------------------------------------------
__global__ __launch_bounds__(256)
void pack_w_f16(const float* __restrict__ W, __half* __restrict__ dst, int K, int N) {
    const int t = blockIdx.x * 256 + threadIdx.x;
    const int kbT = K >> 4;
    const int atom = t >> 5;
    if (atom >= (N >> 3) * kbT) return;
    const int lane = t & 31;
    const int nb = atom / kbT, kb = atom % kbT;
    const int g = lane >> 2, tt = lane & 3;
    const int n = nb * 8 + g;
    const int k0 = kb * 16 + tt * 2;
    uint2 o;
    o.x = h2u(W[(size_t)k0 * N + n],       W[(size_t)(k0 + 1) * N + n]);
    o.y = h2u(W[(size_t)(k0 + 8) * N + n], W[(size_t)(k0 + 9) * N + n]);
    *(uint2*)((char*)dst + (size_t)atom * 256 + lane * 8) = o;
}

// ---------------------------------------------------------------------------
// Gaussian banded smoothing (WIN=16), row-normalized. Reads fp16 y,
// f32 math, writes s in packed fp16 A-fragment layout.
// ---------------------------------------------------------------------------
__global__ __launch_bounds__(256)
void smooth_kernel(const __half* __restrict__ y, __half* __restrict__ spk,
                   const float* __restrict__ sigma) {
    __shared__ float yt[TN + 2 * WIN][64];
    __shared__ float ew[2 * WIN + 1];
    __shared__ float invZ[TN];

    const int n0 = blockIdx.x * TN;
    const int half = blockIdx.y;
    const int bh = blockIdx.z;
    const int b = bh >> 3;
    const int h = bh & 7;
    const int tid = threadIdx.x;

    const __half* ybase = y + (size_t)b * NSEQ * INNER + h * DHEAD + half * 64;
    // 96 rows x 8 chunks of 8 halves = 768 loads
    for (int i = tid; i < (TN + 2 * WIN) * 8; i += 256) {
        const int r = i >> 3;
        const int c = (i & 7) << 3;
        const int m = n0 - WIN + r;
        float2 f0 = make_float2(0.f, 0.f), f1 = f0, f2 = f0, f3 = f0;
        if (m >= 0 && m < NSEQ) {
            const uint4 v = *(const uint4*)(ybase + (size_t)m * INNER + c);
            f0 = __half22float2(*(const __half2*)&v.x);
            f1 = __half22float2(*(const __half2*)&v.y);
            f2 = __half22float2(*(const __half2*)&v.z);
            f3 = __half22float2(*(const __half2*)&v.w);
        }
        *(float4*)&yt[r][c]     = make_float4(f0.x, f0.y, f1.x, f1.y);
        *(float4*)&yt[r][c + 4] = make_float4(f2.x, f2.y, f3.x, f3.y);
    }
    if (tid < 2 * WIN + 1) {
        const float sg = sigma[h];
        const float dd = (float)(tid - WIN);
        ew[tid] = __expf(-dd * dd / (2.f * sg * sg));
    }
    __syncthreads();
    if (tid < TN) {
        const int n = n0 + tid;
        float z = 0.f;
#pragma unroll
        for (int j = 0; j <= 2 * WIN; j++) {
            const int m = n - WIN + j;
            if (m >= 0 && m < NSEQ) z += ew[j];
        }
        invZ[tid] = 1.f / z;
    }
    __syncthreads();

    const int cp = tid & 31;     // channel pair
    const int tg = tid >> 5;     // 0..7
    const int c0 = h * DHEAD + half * 64 + (cp << 1);
    const int kbG = c0 >> 4;
    const int k16 = c0 & 15;
    const int tt = (k16 >> 1) & 3;
    const int khalf = k16 >> 3;
#pragma unroll
    for (int k = 0; k < 8; k++) {
        const int t = tg * 8 + k;
        ull acc = 0ULL;
#pragma unroll
        for (int j = 0; j <= 2 * WIN; j++) {
            const ull w = pack_dup(ew[j]);
            const ull v = *(const ull*)&yt[t + j][cp << 1];
            ffma2(acc, w, v);
        }
        float ax, ay;
        unpack2(acc, ax, ay);
        const float iz = invZ[t];
        const uint32_t pr = h2u(ax * iz, ay * iz);
        const int m = b * NSEQ + n0 + t;
        const int mb = m >> 4;
        const int r16 = m & 15;
        const int g = r16 & 7;
        const int up = r16 >> 3;
        const int lanef = (g << 2) + tt;
        const int reg = (khalf << 1) + up;
        const size_t off = ((size_t)mb * (INNER / 16) + kbG) * 512 + lanef * 16 + reg * 4;
        *(uint32_t*)((char*)spk + off) = pr;
    }
}

// ---------------------------------------------------------------------------
extern "C" void kernel_launch(void* const* d_in, const int* in_sizes, int n_in,
                              void* d_out, int out_size) {
    const float* x     = (const float*)d_in[0];
    const float* Wg    = (const float*)d_in[1];
    const float* Wout  = (const float*)d_in[2];
    const float* sigma = (const float*)d_in[3];
    float* out = (float*)d_out;

    __half *y, *xpk, *spk, *wgpk, *wopk;
    cudaGetSymbolAddress((void**)&y,    g_y);
    cudaGetSymbolAddress((void**)&xpk,  g_xpk);
    cudaGetSymbolAddress((void**)&spk,  g_spk);
    cudaGetSymbolAddress((void**)&wgpk, g_wgpk);
    cudaGetSymbolAddress((void**)&wopk, g_wopk);

    cudaFuncSetAttribute(gemm_f16, cudaFuncAttributeMaxDynamicSharedMemorySize, SMEM_GEMM);

    // prep: pack x, Wg^T, Wout^T to fp16 fragment layouts
    pack_a_f16<<<(MROWS / 16) * (DIM / 16) * 32 / 256, 256>>>(x, xpk, MROWS, DIM);
    pack_w_f16<<<(INNER / 8) * (DIM / 16) * 32 / 256, 256>>>(Wg, wgpk, DIM, INNER);
    pack_w_f16<<<(DIM / 8) * (INNER / 16) * 32 / 256, 256>>>(Wout, wopk, INNER, DIM);

    // GEMM1: y[8192,1024](fp16) = x @ Wg
    gemm_f16<<<dim3(INNER / CTN, MROWS / CTM), 256, SMEM_GEMM>>>(
        xpk, wgpk, y, 1, MROWS, INNER, DIM);

    // banded Gaussian attention -> s (packed fp16)
    smooth_kernel<<<dim3(NSEQ / TN, 2, BATCH * NHEAD), 256>>>(y, spk, sigma);

    // GEMM2: out[8192,512](f32) = s @ Wout
    gemm_f16<<<dim3(DIM / CTN, MROWS / CTM), 256, SMEM_GEMM>>>(
        spk, wopk, out, 0, MROWS, DIM, INNER);
}

// round 12
// speedup vs baseline: 5.5474x; 1.1336x over previous
#include <cuda_runtime.h>
#include <cuda_fp16.h>
#include <cstdint>
#include <cstddef>

// Problem constants
#define BATCH 4
#define NSEQ 2048
#define DIM 512
#define NHEAD 8
#define DHEAD 128
#define INNER 1024
#define MROWS (BATCH*NSEQ)  // 8192

#define WIN 16
#define TN 64

// ---------------- scratch (allocation-free rule) ----------------
// fp16 packed operands in m16n8k16 fragment order.
// A atom = 16x16 f16 = 512B: lane*16 -> [a0,a1,a2,a3]. B atom = 8x16 = 256B.
__device__ __align__(16) __half g_y[MROWS * INNER];     // gemm1 out, fp16 row-major
__device__ __align__(16) __half g_xpk[MROWS * DIM];
__device__ __align__(16) __half g_spk[MROWS * INNER];
__device__ __align__(16) __half g_wgpk[DIM * INNER];    // Wg^T packed
__device__ __align__(16) __half g_wopk[INNER * DIM];    // Wout^T packed

// ---------------- helpers ----------------
typedef unsigned long long ull;
__device__ __forceinline__ ull pack_dup(float a) {
    ull r; asm("mov.b64 %0, {%1, %1};" : "=l"(r) : "f"(a)); return r;
}
__device__ __forceinline__ void ffma2(ull& d, ull a, ull b) {
    asm("fma.rn.f32x2 %0, %1, %2, %0;" : "+l"(d) : "l"(a), "l"(b));
}
__device__ __forceinline__ void unpack2(ull v, float& lo, float& hi) {
    asm("mov.b64 {%0, %1}, %2;" : "=f"(lo), "=f"(hi) : "l"(v));
}
__device__ __forceinline__ uint32_t smem_to_u32(const void* p) {
    uint32_t a;
    asm("{ .reg .u64 t; cvta.to.shared.u64 t, %1; cvt.u32.u64 %0, t; }" : "=r"(a) : "l"(p));
    return a;
}
__device__ __forceinline__ void cp16(uint32_t dst, const void* src) {
    asm volatile("cp.async.cg.shared.global [%0], [%1], 16;" :: "r"(dst), "l"(src) : "memory");
}
#define CP_COMMIT() asm volatile("cp.async.commit_group;" ::: "memory")
#define CP_WAIT1()  asm volatile("cp.async.wait_group 1;" ::: "memory")

__device__ __forceinline__ void lds128(uint32_t addr, uint32_t* r) {
    asm volatile("ld.shared.v4.b32 {%0,%1,%2,%3}, [%4];"
                 : "=r"(r[0]), "=r"(r[1]), "=r"(r[2]), "=r"(r[3]) : "r"(addr));
}
__device__ __forceinline__ void lds64(uint32_t addr, uint32_t* r) {
    asm volatile("ld.shared.v2.b32 {%0,%1}, [%2];"
                 : "=r"(r[0]), "=r"(r[1]) : "r"(addr));
}
__device__ __forceinline__ void mma_f16(float* d, const uint32_t* a, const uint32_t* b) {
    asm volatile("mma.sync.aligned.m16n8k16.row.col.f32.f16.f16.f32 "
                 "{%0,%1,%2,%3}, {%4,%5,%6,%7}, {%8,%9}, {%0,%1,%2,%3};"
                 : "+f"(d[0]), "+f"(d[1]), "+f"(d[2]), "+f"(d[3])
                 : "r"(a[0]), "r"(a[1]), "r"(a[2]), "r"(a[3]), "r"(b[0]), "r"(b[1]));
}
__device__ __forceinline__ uint32_t h2u(float a, float b) {
    __half2 h = __floats2half2_rn(a, b);
    return *(uint32_t*)&h;
}

// ---------------------------------------------------------------------------
// fp16 GEMM: C[M,N] = A[M,K] @ B^T, operands pre-packed in fragment order.
// CTA tile 128x128, K-chunk 64 (4 k16), 8 warps (2m x 4n), warp tile 64x32.
// 3-stage cp.async pipeline (32KB/stage). C written f32 or f16 (halfOut).
// ---------------------------------------------------------------------------
#define CTM 128
#define CTN 128
#define STG_A_BYTES 16384      // 32 A atoms (8 mb x 4 kb) x 512B
#define STG_B_BYTES 16384      // 64 B atoms (16 nb x 4 kb) x 256B
#define STAGE_BYTES (STG_A_BYTES + STG_B_BYTES)  // 32768
#define SMEM_GEMM (3 * STAGE_BYTES)              // 98304

__global__ __launch_bounds__(256, 2)
void gemm_f16(const __half* __restrict__ Apk, const __half* __restrict__ Bpk,
              void* __restrict__ Cv, int halfOut, int M, int N, int K) {
    extern __shared__ char smem[];
    const uint32_t sb = smem_to_u32(smem);
    const int tid = threadIdx.x;
    const int wid = tid >> 5;
    const int lane = tid & 31;
    const int row0 = blockIdx.y << 7;
    const int col0 = blockIdx.x << 7;
    const int kbT = K >> 4;             // k16 blocks total (GMEM layout unit)
    const int mb0 = row0 >> 4;
    const int nb0 = col0 >> 3;

    const int wm = wid & 1;             // 4 m-blocks (64 rows)
    const int wn = wid >> 1;            // 4 n-blocks (32 cols)

    auto load_stage = [&](int buf, int kt) {
        const uint32_t st = sb + buf * STAGE_BYTES;
        const int kb0 = kt << 2;        // 4 k16 per chunk
        // A: 32 atoms x 512B = 1024 chunks of 16B
#pragma unroll
        for (int r = 0; r < 4; r++) {
            const int i = tid + (r << 8);
            const int atomL = i >> 5;               // 0..31
            const int inner = (i & 31) << 4;
            const int mbL = atomL >> 2, kbL = atomL & 3;
            const size_t g = ((size_t)(mb0 + mbL) * kbT + kb0 + kbL) * 512 + inner;
            cp16(st + (atomL << 9) + inner, (const char*)Apk + g);
        }
        // B: 64 atoms x 256B = 1024 chunks
#pragma unroll
        for (int r = 0; r < 4; r++) {
            const int i = tid + (r << 8);
            const int atomL = i >> 4;               // 0..63
            const int inner = (i & 15) << 4;
            const int nbL = atomL >> 2, kbL = atomL & 3;
            const size_t g = ((size_t)(nb0 + nbL) * kbT + kb0 + kbL) * 256 + inner;
            cp16(st + STG_A_BYTES + (atomL << 8) + inner, (const char*)Bpk + g);
        }
    };

    float d[4][4][4];
#pragma unroll
    for (int i = 0; i < 4; i++)
#pragma unroll
        for (int j = 0; j < 4; j++)
#pragma unroll
            for (int q = 0; q < 4; q++) d[i][j][q] = 0.f;

    const int KT = K >> 6;              // 64-k chunks
    load_stage(0, 0); CP_COMMIT();
    load_stage(1, 1); CP_COMMIT();

    const uint32_t la16 = (uint32_t)lane << 4;
    const uint32_t la8  = (uint32_t)lane << 3;

    int cur = 0, nxt2 = 2;
    for (int kt = 0; kt < KT; kt++) {
        CP_WAIT1();
        __syncthreads();
        if (kt + 2 < KT) load_stage(nxt2, kt + 2);
        CP_COMMIT();

        const uint32_t st = sb + cur * STAGE_BYTES;
#pragma unroll
        for (int ki = 0; ki < 4; ki++) {
            uint32_t a[4][4], b[4][2];
#pragma unroll
            for (int mi = 0; mi < 4; mi++)
                lds128(st + (uint32_t)(((((wm << 2) + mi) << 2) + ki) << 9) + la16, a[mi]);
#pragma unroll
            for (int ni = 0; ni < 4; ni++)
                lds64(st + STG_A_BYTES
                      + (uint32_t)(((((wn << 2) + ni) << 2) + ki) << 8) + la8, b[ni]);
#pragma unroll
            for (int mi = 0; mi < 4; mi++)
#pragma unroll
                for (int ni = 0; ni < 4; ni++)
                    mma_f16(d[mi][ni], a[mi], b[ni]);
        }
        cur  = (cur == 2)  ? 0 : cur + 1;
        nxt2 = (nxt2 == 2) ? 0 : nxt2 + 1;
    }

    // epilogue: atom (mi, ni) -> rows (g, g+8), cols (tg*2, +1)
    const int gr = lane >> 2;
    const int tg = lane & 3;
    if (halfOut) {
        __half* C = (__half*)Cv;
#pragma unroll
        for (int mi = 0; mi < 4; mi++) {
            const int r0 = row0 + (wm << 6) + (mi << 4) + gr;
#pragma unroll
            for (int ni = 0; ni < 4; ni++) {
                const int c = col0 + (wn << 5) + (ni << 3) + (tg << 1);
                *(uint32_t*)&C[(size_t)r0 * N + c]       = h2u(d[mi][ni][0], d[mi][ni][1]);
                *(uint32_t*)&C[(size_t)(r0 + 8) * N + c] = h2u(d[mi][ni][2], d[mi][ni][3]);
            }
        }
    } else {
        float* C = (float*)Cv;
#pragma unroll
        for (int mi = 0; mi < 4; mi++) {
            const int r0 = row0 + (wm << 6) + (mi << 4) + gr;
#pragma unroll
            for (int ni = 0; ni < 4; ni++) {
                const int c = col0 + (wn << 5) + (ni << 3) + (tg << 1);
                *(float2*)&C[(size_t)r0 * N + c]       = make_float2(d[mi][ni][0], d[mi][ni][1]);
                *(float2*)&C[(size_t)(r0 + 8) * N + c] = make_float2(d[mi][ni][2], d[mi][ni][3]);
            }
        }
    }
}

// ---------------------------------------------------------------------------
// merged pack: blocks [0,2048) pack x; [2048,2560) Wg^T; [2560,3072) Wout^T
// ---------------------------------------------------------------------------
__device__ __forceinline__ void pack_a_body(const float* src, __half* dst,
                                            int t, int M, int K) {
    const int kbT = K >> 4;
    const int atom = t >> 5;
    if (atom >= (M >> 4) * kbT) return;
    const int lane = t & 31;
    const int mb = atom / kbT, kb = atom % kbT;
    const int g = lane >> 2, tt = lane & 3;
    const int r0 = mb * 16 + g, r1 = r0 + 8;
    const int c0 = kb * 16 + tt * 2;
    const float2 v0 = *(const float2*)(src + (size_t)r0 * K + c0);
    const float2 v1 = *(const float2*)(src + (size_t)r1 * K + c0);
    const float2 v2 = *(const float2*)(src + (size_t)r0 * K + c0 + 8);
    const float2 v3 = *(const float2*)(src + (size_t)r1 * K + c0 + 8);
    uint4 o;
    o.x = h2u(v0.x, v0.y);
    o.y = h2u(v1.x, v1.y);
    o.z = h2u(v2.x, v2.y);
    o.w = h2u(v3.x, v3.y);
    *(uint4*)((char*)dst + (size_t)atom * 512 + lane * 16) = o;
}
__device__ __forceinline__ void pack_w_body(const float* W, __half* dst,
                                            int t, int K, int N) {
    const int kbT = K >> 4;
    const int atom = t >> 5;
    if (atom >= (N >> 3) * kbT) return;
    const int lane = t & 31;
    const int nb = atom / kbT, kb = atom % kbT;
    const int g = lane >> 2, tt = lane & 3;
    const int n = nb * 8 + g;
    const int k0 = kb * 16 + tt * 2;
    uint2 o;
    o.x = h2u(W[(size_t)k0 * N + n],       W[(size_t)(k0 + 1) * N + n]);
    o.y = h2u(W[(size_t)(k0 + 8) * N + n], W[(size_t)(k0 + 9) * N + n]);
    *(uint2*)((char*)dst + (size_t)atom * 256 + lane * 8) = o;
}

__global__ __launch_bounds__(256)
void pack_all(const float* __restrict__ x, const float* __restrict__ Wg,
              const float* __restrict__ Wout, __half* __restrict__ xpk,
              __half* __restrict__ wgpk, __half* __restrict__ wopk) {
    const int bid = blockIdx.x;
    if (bid < 2048) {
        pack_a_body(x, xpk, bid * 256 + threadIdx.x, MROWS, DIM);
    } else if (bid < 2560) {
        pack_w_body(Wg, wgpk, (bid - 2048) * 256 + threadIdx.x, DIM, INNER);
    } else {
        pack_w_body(Wout, wopk, (bid - 2560) * 256 + threadIdx.x, INNER, DIM);
    }
}

// ---------------------------------------------------------------------------
// Gaussian banded smoothing (WIN=16), row-normalized. Reads fp16 y,
// f32 math, writes s in packed fp16 A-fragment layout.
// ---------------------------------------------------------------------------
__global__ __launch_bounds__(256)
void smooth_kernel(const __half* __restrict__ y, __half* __restrict__ spk,
                   const float* __restrict__ sigma) {
    __shared__ float yt[TN + 2 * WIN][64];
    __shared__ float ew[2 * WIN + 1];
    __shared__ float invZ[TN];

    const int n0 = blockIdx.x * TN;
    const int half = blockIdx.y;
    const int bh = blockIdx.z;
    const int b = bh >> 3;
    const int h = bh & 7;
    const int tid = threadIdx.x;

    const __half* ybase = y + (size_t)b * NSEQ * INNER + h * DHEAD + half * 64;
    for (int i = tid; i < (TN + 2 * WIN) * 8; i += 256) {
        const int r = i >> 3;
        const int c = (i & 7) << 3;
        const int m = n0 - WIN + r;
        float2 f0 = make_float2(0.f, 0.f), f1 = f0, f2 = f0, f3 = f0;
        if (m >= 0 && m < NSEQ) {
            const uint4 v = *(const uint4*)(ybase + (size_t)m * INNER + c);
            f0 = __half22float2(*(const __half2*)&v.x);
            f1 = __half22float2(*(const __half2*)&v.y);
            f2 = __half22float2(*(const __half2*)&v.z);
            f3 = __half22float2(*(const __half2*)&v.w);
        }
        *(float4*)&yt[r][c]     = make_float4(f0.x, f0.y, f1.x, f1.y);
        *(float4*)&yt[r][c + 4] = make_float4(f2.x, f2.y, f3.x, f3.y);
    }
    if (tid < 2 * WIN + 1) {
        const float sg = sigma[h];
        const float dd = (float)(tid - WIN);
        ew[tid] = __expf(-dd * dd / (2.f * sg * sg));
    }
    __syncthreads();
    if (tid < TN) {
        const int n = n0 + tid;
        float z = 0.f;
#pragma unroll
        for (int j = 0; j <= 2 * WIN; j++) {
            const int m = n - WIN + j;
            if (m >= 0 && m < NSEQ) z += ew[j];
        }
        invZ[tid] = 1.f / z;
    }
    __syncthreads();

    const int cp = tid & 31;
    const int tg = tid >> 5;
    const int c0 = h * DHEAD + half * 64 + (cp << 1);
    const int kbG = c0 >> 4;
    const int k16 = c0 & 15;
    const int tt = (k16 >> 1) & 3;
    const int khalf = k16 >> 3;
#pragma unroll
    for (int k = 0; k < 8; k++) {
        const int t = tg * 8 + k;
        ull acc = 0ULL;
#pragma unroll
        for (int j = 0; j <= 2 * WIN; j++) {
            const ull w = pack_dup(ew[j]);
            const ull v = *(const ull*)&yt[t + j][cp << 1];
            ffma2(acc, w, v);
        }
        float ax, ay;
        unpack2(acc, ax, ay);
        const float iz = invZ[t];
        const uint32_t pr = h2u(ax * iz, ay * iz);
        const int m = b * NSEQ + n0 + t;
        const int mb = m >> 4;
        const int r16 = m & 15;
        const int g = r16 & 7;
        const int up = r16 >> 3;
        const int lanef = (g << 2) + tt;
        const int reg = (khalf << 1) + up;
        const size_t off = ((size_t)mb * (INNER / 16) + kbG) * 512 + lanef * 16 + reg * 4;
        *(uint32_t*)((char*)spk + off) = pr;
    }
}

// ---------------------------------------------------------------------------
extern "C" void kernel_launch(void* const* d_in, const int* in_sizes, int n_in,
                              void* d_out, int out_size) {
    const float* x     = (const float*)d_in[0];
    const float* Wg    = (const float*)d_in[1];
    const float* Wout  = (const float*)d_in[2];
    const float* sigma = (const float*)d_in[3];
    float* out = (float*)d_out;

    __half *y, *xpk, *spk, *wgpk, *wopk;
    cudaGetSymbolAddress((void**)&y,    g_y);
    cudaGetSymbolAddress((void**)&xpk,  g_xpk);
    cudaGetSymbolAddress((void**)&spk,  g_spk);
    cudaGetSymbolAddress((void**)&wgpk, g_wgpk);
    cudaGetSymbolAddress((void**)&wopk, g_wopk);

    cudaFuncSetAttribute(gemm_f16, cudaFuncAttributeMaxDynamicSharedMemorySize, SMEM_GEMM);

    // prep: pack x, Wg^T, Wout^T to fp16 fragment layouts (one launch)
    pack_all<<<3072, 256>>>(x, Wg, Wout, xpk, wgpk, wopk);

    // GEMM1: y[8192,1024](fp16) = x @ Wg
    gemm_f16<<<dim3(INNER / CTN, MROWS / CTM), 256, SMEM_GEMM>>>(
        xpk, wgpk, y, 1, MROWS, INNER, DIM);

    // banded Gaussian attention -> s (packed fp16)
    smooth_kernel<<<dim3(NSEQ / TN, 2, BATCH * NHEAD), 256>>>(y, spk, sigma);

    // GEMM2: out[8192,512](f32) = s @ Wout
    gemm_f16<<<dim3(DIM / CTN, MROWS / CTM), 256, SMEM_GEMM>>>(
        spk, wopk, out, 0, MROWS, DIM, INNER);
}